// round 9
// baseline (speedup 1.0000x reference)
#include <cuda_runtime.h>

// SpikeLayer: T=16 timesteps, per-step batch B=512, features D=8192.
// For each (b, d): V += x[t]; if |V| > 1 -> V = 0; out[t] = V.
// R6: persistent single-wave grid (1024 CTAs, ~7/SM), each CTA grid-strides
// over 4 column-chunks. Removes wave transitions / tail imbalance so DRAM
// stays saturated continuously. GRP=4 load/compute/store batching retained.

#define TT 16
#define BB 512
#define DD 8192
#define STRIDE4 ((BB * DD) / 4)   // float4 per timestep slab = 1,048,576
#define GRP 4
#define NBLK 1024
#define NITER (STRIDE4 / (NBLK * 256))   // = 4

__global__ __launch_bounds__(256) void spike_kernel(
    const float4* __restrict__ in, float4* __restrict__ out)
{
    const unsigned base = blockIdx.x * 256u + threadIdx.x;
    const unsigned step = NBLK * 256u;   // 262,144

#pragma unroll 1
    for (int it = 0; it < NITER; ++it) {
        const unsigned idx = base + (unsigned)it * step;
        const float4* __restrict__ p = in  + idx;
        float4*       __restrict__ q = out + idx;

        float4 V = make_float4(0.f, 0.f, 0.f, 0.f);
        float4 x[GRP];

#pragma unroll
        for (int g = 0; g < TT / GRP; ++g) {
#pragma unroll
            for (int t = 0; t < GRP; ++t)
                x[t] = __ldcs(p + (unsigned)(g * GRP + t) * STRIDE4);

#pragma unroll
            for (int t = 0; t < GRP; ++t) {
                V.x += x[t].x;  V.x = (fabsf(V.x) > 1.0f) ? 0.0f : V.x;
                V.y += x[t].y;  V.y = (fabsf(V.y) > 1.0f) ? 0.0f : V.y;
                V.z += x[t].z;  V.z = (fabsf(V.z) > 1.0f) ? 0.0f : V.z;
                V.w += x[t].w;  V.w = (fabsf(V.w) > 1.0f) ? 0.0f : V.w;
                x[t] = V;
            }

#pragma unroll
            for (int t = 0; t < GRP; ++t)
                __stcs(q + (unsigned)(g * GRP + t) * STRIDE4, x[t]);
        }
    }
}

extern "C" void kernel_launch(void* const* d_in, const int* in_sizes, int n_in,
                              void* d_out, int out_size)
{
    (void)in_sizes; (void)n_in; (void)out_size;
    const float4* in  = (const float4*)d_in[0];
    float4*       out = (float4*)d_out;

    spike_kernel<<<NBLK, 256>>>(in, out);
}

// round 10
// speedup vs baseline: 1.0021x; 1.0021x over previous
#include <cuda_runtime.h>

// SpikeLayer: T=16 timesteps, per-step batch B=512, features D=8192.
// For each (b, d): V += x[t]; if |V| > 1 -> V = 0; out[t] = V.
// R6: persistent single-wave grid (1024 CTAs, ~7/SM), each CTA grid-strides
// over 4 column-chunks. Removes wave transitions / tail imbalance so DRAM
// stays saturated continuously. GRP=4 load/compute/store batching retained.

#define TT 16
#define BB 512
#define DD 8192
#define STRIDE4 ((BB * DD) / 4)   // float4 per timestep slab = 1,048,576
#define GRP 4
#define NBLK 1024
#define NITER (STRIDE4 / (NBLK * 256))   // = 4

__global__ __launch_bounds__(256) void spike_kernel(
    const float4* __restrict__ in, float4* __restrict__ out)
{
    const unsigned base = blockIdx.x * 256u + threadIdx.x;
    const unsigned step = NBLK * 256u;   // 262,144

#pragma unroll 1
    for (int it = 0; it < NITER; ++it) {
        const unsigned idx = base + (unsigned)it * step;
        const float4* __restrict__ p = in  + idx;
        float4*       __restrict__ q = out + idx;

        float4 V = make_float4(0.f, 0.f, 0.f, 0.f);
        float4 x[GRP];

#pragma unroll
        for (int g = 0; g < TT / GRP; ++g) {
#pragma unroll
            for (int t = 0; t < GRP; ++t)
                x[t] = __ldcs(p + (unsigned)(g * GRP + t) * STRIDE4);

#pragma unroll
            for (int t = 0; t < GRP; ++t) {
                V.x += x[t].x;  V.x = (fabsf(V.x) > 1.0f) ? 0.0f : V.x;
                V.y += x[t].y;  V.y = (fabsf(V.y) > 1.0f) ? 0.0f : V.y;
                V.z += x[t].z;  V.z = (fabsf(V.z) > 1.0f) ? 0.0f : V.z;
                V.w += x[t].w;  V.w = (fabsf(V.w) > 1.0f) ? 0.0f : V.w;
                x[t] = V;
            }

#pragma unroll
            for (int t = 0; t < GRP; ++t)
                __stcs(q + (unsigned)(g * GRP + t) * STRIDE4, x[t]);
        }
    }
}

extern "C" void kernel_launch(void* const* d_in, const int* in_sizes, int n_in,
                              void* d_out, int out_size)
{
    (void)in_sizes; (void)n_in; (void)out_size;
    const float4* in  = (const float4*)d_in[0];
    float4*       out = (float4*)d_out;

    spike_kernel<<<NBLK, 256>>>(in, out);
}

// round 11
// speedup vs baseline: 1.0849x; 1.0826x over previous
#include <cuda_runtime.h>

// SpikeLayer: T=16 timesteps, per-step batch B=512, features D=8192.
// For each (b, d): V += x[t]; if |V| > 1 -> V = 0; out[t] = V.
// R10: revert persistent grid (regressed: fewer CTAs starved L1tex/DRAM
// queues). Back to 4096-CTA single-pass layout; tighten load batch to
// GRP=2 so oe*MLP_p1 (~10) drops below the L1tex contention threshold
// (~16) and read/write streams interleave in shorter bursts.

#define TT 16
#define BB 512
#define DD 8192
#define STRIDE4 ((BB * DD) / 4)   // float4 per timestep slab = 1,048,576
#define GRP 2

__global__ __launch_bounds__(256) void spike_kernel(
    const float4* __restrict__ in, float4* __restrict__ out)
{
    const unsigned idx = blockIdx.x * 256u + threadIdx.x;  // 0 .. STRIDE4-1
    const float4* __restrict__ p = in  + idx;
    float4*       __restrict__ q = out + idx;

    float4 V = make_float4(0.f, 0.f, 0.f, 0.f);
    float4 x[GRP];

#pragma unroll
    for (int g = 0; g < TT / GRP; ++g) {
        // Batch GRP streaming loads
#pragma unroll
        for (int t = 0; t < GRP; ++t)
            x[t] = __ldcs(p + (unsigned)(g * GRP + t) * STRIDE4);

        // Dependency chain in registers; overwrite x[] with outputs
#pragma unroll
        for (int t = 0; t < GRP; ++t) {
            V.x += x[t].x;  V.x = (fabsf(V.x) > 1.0f) ? 0.0f : V.x;
            V.y += x[t].y;  V.y = (fabsf(V.y) > 1.0f) ? 0.0f : V.y;
            V.z += x[t].z;  V.z = (fabsf(V.z) > 1.0f) ? 0.0f : V.z;
            V.w += x[t].w;  V.w = (fabsf(V.w) > 1.0f) ? 0.0f : V.w;
            x[t] = V;
        }

        // Batch GRP streaming stores
#pragma unroll
        for (int t = 0; t < GRP; ++t)
            __stcs(q + (unsigned)(g * GRP + t) * STRIDE4, x[t]);
    }
}

extern "C" void kernel_launch(void* const* d_in, const int* in_sizes, int n_in,
                              void* d_out, int out_size)
{
    (void)in_sizes; (void)n_in; (void)out_size;
    const float4* in  = (const float4*)d_in[0];
    float4*       out = (float4*)d_out;

    const int threads = 256;
    const int blocks  = STRIDE4 / threads;  // 4096
    spike_kernel<<<blocks, threads>>>(in, out);
}

// round 12
// speedup vs baseline: 1.1029x; 1.0166x over previous
#include <cuda_runtime.h>

// SpikeLayer: T=16 timesteps, per-step batch B=512, features D=8192.
// For each (b, d): V += x[t]; if |V| > 1 -> V = 0; out[t] = V.
// R11: best layout (4096 CTAs, GRP=4 batches) + explicit double-buffered
// software pipeline: batch g+1's loads issue BEFORE batch g's compute and
// stores, so the DRAM read stream never drains during write bursts
// (R/W turnaround bubbles were the residual DRAM idle).

#define TT 16
#define BB 512
#define DD 8192
#define STRIDE4 ((BB * DD) / 4)   // float4 per timestep slab = 1,048,576
#define GRP 4
#define NG (TT / GRP)             // 4 groups

__global__ __launch_bounds__(256) void spike_kernel(
    const float4* __restrict__ in, float4* __restrict__ out)
{
    const unsigned idx = blockIdx.x * 256u + threadIdx.x;  // 0 .. STRIDE4-1
    const float4* __restrict__ p = in  + idx;
    float4*       __restrict__ q = out + idx;

    float4 V = make_float4(0.f, 0.f, 0.f, 0.f);
    float4 cur[GRP], nxt[GRP];

    // Prologue: load group 0
#pragma unroll
    for (int t = 0; t < GRP; ++t)
        cur[t] = __ldcs(p + (unsigned)t * STRIDE4);

#pragma unroll
    for (int g = 0; g < NG; ++g) {
        // Prefetch next group's loads before touching this group's stores
        if (g + 1 < NG) {
#pragma unroll
            for (int t = 0; t < GRP; ++t)
                nxt[t] = __ldcs(p + (unsigned)((g + 1) * GRP + t) * STRIDE4);
        }

        // Dependency chain in registers; overwrite cur[] with outputs
#pragma unroll
        for (int t = 0; t < GRP; ++t) {
            V.x += cur[t].x;  V.x = (fabsf(V.x) > 1.0f) ? 0.0f : V.x;
            V.y += cur[t].y;  V.y = (fabsf(V.y) > 1.0f) ? 0.0f : V.y;
            V.z += cur[t].z;  V.z = (fabsf(V.z) > 1.0f) ? 0.0f : V.z;
            V.w += cur[t].w;  V.w = (fabsf(V.w) > 1.0f) ? 0.0f : V.w;
            cur[t] = V;
        }

        // Store this group (reads for g+1 already in flight)
#pragma unroll
        for (int t = 0; t < GRP; ++t)
            __stcs(q + (unsigned)(g * GRP + t) * STRIDE4, cur[t]);

        // Rotate buffers (register renaming, no real moves after unroll)
        if (g + 1 < NG) {
#pragma unroll
            for (int t = 0; t < GRP; ++t)
                cur[t] = nxt[t];
        }
    }
}

extern "C" void kernel_launch(void* const* d_in, const int* in_sizes, int n_in,
                              void* d_out, int out_size)
{
    (void)in_sizes; (void)n_in; (void)out_size;
    const float4* in  = (const float4*)d_in[0];
    float4*       out = (float4*)d_out;

    const int threads = 256;
    const int blocks  = STRIDE4 / threads;  // 4096
    spike_kernel<<<blocks, threads>>>(in, out);
}